// round 2
// baseline (speedup 1.0000x reference)
#include <cuda_runtime.h>

#define BB  64
#define INN 512
#define HH  512
#define HID 16

// Scratch tables (allocation-free: __device__ globals).
// g_P[b, i, k] = pre[b,i] * W1[k,0] + b1[k]
// g_Q[b, j, k] = post[b,j] * W1[k,1]
__device__ float g_P[BB * INN * HID];
__device__ float g_Q[BB * HH * HID];

// ---------------- packed f32x2 helpers (Blackwell sm_100+) ----------------
static __device__ __forceinline__ unsigned long long f2_add(unsigned long long a, unsigned long long b) {
    unsigned long long r;
    asm("add.rn.f32x2 %0, %1, %2;" : "=l"(r) : "l"(a), "l"(b));
    return r;
}
static __device__ __forceinline__ unsigned long long f2_fma(unsigned long long a, unsigned long long b, unsigned long long c) {
    unsigned long long r;
    asm("fma.rn.f32x2 %0, %1, %2, %3;" : "=l"(r) : "l"(a), "l"(b), "l"(c));
    return r;
}
static __device__ __forceinline__ unsigned long long f2_pack(float x, float y) {
    unsigned long long r;
    asm("mov.b64 %0, {%1, %2};" : "=l"(r) : "f"(x), "f"(y));
    return r;
}
static __device__ __forceinline__ float2 f2_unpack(unsigned long long v) {
    float2 r;
    asm("mov.b64 {%0, %1}, %2;" : "=f"(r.x), "=f"(r.y) : "l"(v));
    return r;
}
static __device__ __forceinline__ unsigned long long f2_relu(unsigned long long v) {
    float2 t = f2_unpack(v);
    return f2_pack(fmaxf(t.x, 0.0f), fmaxf(t.y, 0.0f));
}

// ---------------- prep: build P and Q tables ----------------
__global__ void prep_kernel(const float* __restrict__ pre,
                            const float* __restrict__ post,
                            const float* __restrict__ W1,
                            const float* __restrict__ b1) {
    int t = blockIdx.x * blockDim.x + threadIdx.x;   // 0 .. B*512-1 (B*IN == B*H)
    if (t >= BB * INN) return;
    float p = pre[t];
    float q = post[t];
    float4* Pp = reinterpret_cast<float4*>(&g_P[(size_t)t * HID]);
    float4* Qp = reinterpret_cast<float4*>(&g_Q[(size_t)t * HID]);
#pragma unroll
    for (int k4 = 0; k4 < HID / 4; ++k4) {
        float pv[4], qv[4];
#pragma unroll
        for (int r = 0; r < 4; ++r) {
            int k = k4 * 4 + r;
            float u  = W1[k * 3 + 0];
            float v  = W1[k * 3 + 1];
            float bk = b1[k];
            pv[r] = fmaf(p, u, bk);
            qv[r] = q * v;
        }
        Pp[k4] = make_float4(pv[0], pv[1], pv[2], pv[3]);
        Qp[k4] = make_float4(qv[0], qv[1], qv[2], qv[3]);
    }
}

// ---------------- main: out[i,j] ----------------
// Block: 128 threads = 16 (ti) x 8 (tj); each thread computes 1 i x 4 j.
// Tile: 16 i x 32 j. Grid: (H/32, IN/16) = (16, 32) = 512 blocks.
__global__ __launch_bounds__(128, 4)
void plasticity_main(const float* __restrict__ weight,
                     const float* __restrict__ W1,
                     const float* __restrict__ W2,
                     const float* __restrict__ b2,
                     float* __restrict__ out) {
    const int ti = threadIdx.x >> 3;          // 0..15
    const int tj = threadIdx.x & 7;           // 0..7
    const int i  = blockIdx.y * 16 + ti;
    const int j0 = blockIdx.x * 32 + tj * 4;

    // Loop-invariant packed constants: t2 = W1[:,2] pairs, w2p = W2 pairs.
    unsigned long long t2[8], w2p[8];
#pragma unroll
    for (int kp = 0; kp < 8; ++kp) {
        t2[kp]  = f2_pack(W1[(2 * kp) * 3 + 2], W1[(2 * kp + 1) * 3 + 2]);
        w2p[kp] = f2_pack(W2[2 * kp], W2[2 * kp + 1]);
    }

    // w_ij for this thread's 4 contiguous j, broadcast into both f32x2 lanes.
    float4 wv = *reinterpret_cast<const float4*>(&weight[(size_t)i * HH + j0]);
    unsigned long long wij2[4] = {
        f2_pack(wv.x, wv.x), f2_pack(wv.y, wv.y),
        f2_pack(wv.z, wv.z), f2_pack(wv.w, wv.w)
    };

    // Dual accumulator chains per j (even/odd kp) for ILP. 0ull == packed +0.0f.
    unsigned long long acc[4][2];
#pragma unroll
    for (int jj = 0; jj < 4; ++jj) { acc[jj][0] = 0ull; acc[jj][1] = 0ull; }

#pragma unroll 1
    for (int b = 0; b < BB; ++b) {
        // P row for (b, i): 16 floats = 4x LDG.128 (64B unique per warp, broadcast-coalesced)
        const ulonglong2* __restrict__ prow =
            reinterpret_cast<const ulonglong2*>(&g_P[((size_t)b * INN + i) * HID]);
        unsigned long long pv[8];
#pragma unroll
        for (int c = 0; c < 4; ++c) { ulonglong2 v = prow[c]; pv[2 * c] = v.x; pv[2 * c + 1] = v.y; }

        const ulonglong2* __restrict__ qrow0 =
            reinterpret_cast<const ulonglong2*>(&g_Q[((size_t)b * HH + j0) * HID]);
#pragma unroll
        for (int jj = 0; jj < 4; ++jj) {
            unsigned long long qv[8];
            const ulonglong2* qrow = qrow0 + jj * 4;
#pragma unroll
            for (int c = 0; c < 4; ++c) { ulonglong2 v = qrow[c]; qv[2 * c] = v.x; qv[2 * c + 1] = v.y; }
#pragma unroll
            for (int kp = 0; kp < 8; ++kp) {
                unsigned long long s = f2_add(pv[kp], qv[kp]);          // P + Q      (2 elems)
                unsigned long long x = f2_fma(wij2[jj], t2[kp], s);     // + w_ij*t_k (2 elems)
                unsigned long long r = f2_relu(x);                      // relu
                acc[jj][kp & 1] = f2_fma(r, w2p[kp], acc[jj][kp & 1]);  // += relu * W2_k
            }
        }
    }

    const float inv_b = 1.0f / (float)BB;
    const float bias2 = b2[0];
    float4 res;
#pragma unroll
    for (int jj = 0; jj < 4; ++jj) {
        float2 a = f2_unpack(f2_add(acc[jj][0], acc[jj][1]));
        (&res.x)[jj] = fmaf(a.x + a.y, inv_b, bias2);
    }
    *reinterpret_cast<float4*>(&out[(size_t)i * HH + j0]) = res;
}

// ---------------- launch ----------------
extern "C" void kernel_launch(void* const* d_in, const int* in_sizes, int n_in,
                              void* d_out, int out_size) {
    const float* pre    = (const float*)d_in[0];
    const float* post   = (const float*)d_in[1];
    const float* weight = (const float*)d_in[2];
    const float* W1     = (const float*)d_in[3];
    const float* b1     = (const float*)d_in[4];
    const float* W2     = (const float*)d_in[5];
    const float* b2     = (const float*)d_in[6];
    float* out = (float*)d_out;

    prep_kernel<<<(BB * INN + 255) / 256, 256>>>(pre, post, W1, b1);
    plasticity_main<<<dim3(HH / 32, INN / 16), 128>>>(weight, W1, W2, b2, out);
}

// round 3
// speedup vs baseline: 5.1779x; 5.1779x over previous
#include <cuda_runtime.h>

#define BB  64
#define INN 512
#define HH  512
#define HID 16

// ---------------- packed f32x2 helpers (Blackwell sm_100+) ----------------
typedef unsigned long long u64;

static __device__ __forceinline__ u64 f2_fma(u64 a, u64 b, u64 c) {
    u64 r;
    asm("fma.rn.f32x2 %0, %1, %2, %3;" : "=l"(r) : "l"(a), "l"(b), "l"(c));
    return r;
}
static __device__ __forceinline__ u64 f2_pack(float x, float y) {
    u64 r;
    asm("mov.b64 %0, {%1, %2};" : "=l"(r) : "f"(x), "f"(y));
    return r;
}
static __device__ __forceinline__ float2 f2_unpack(u64 v) {
    float2 r;
    asm("mov.b64 {%0, %1}, %2;" : "=f"(r.x), "=f"(r.y) : "l"(v));
    return r;
}
// relu: unpack/pack are register aliasing (free); 2x FMNMX on the alu pipe.
static __device__ __forceinline__ u64 f2_relu(u64 v) {
    float2 t = f2_unpack(v);
    return f2_pack(fmaxf(t.x, 0.0f), fmaxf(t.y, 0.0f));
}

// ---------------- fused kernel ----------------
// out[i,j] = (1/B) * sum_b sum_k relu(pre[b,i]*u_k + post[b,j]*v_k + w_ij*t_k + b1_k) * W2_k + b2
//
// Block: 128 threads = 8 (ti) x 16 (tj). Thread tile: 2 i x 4 j.
// Block tile: 16 i x 64 j. Grid: (H/64, IN/16) = (8, 32) = 256 blocks.
// All k-vectors live in loop-invariant packed registers; per-b loads are just
// 2 pre scalars (warp broadcast) + 1 post float4 (coalesced) per thread.
__global__ __launch_bounds__(128, 2)
void plasticity_fused(const float* __restrict__ pre,
                      const float* __restrict__ post,
                      const float* __restrict__ weight,
                      const float* __restrict__ W1,
                      const float* __restrict__ b1,
                      const float* __restrict__ W2,
                      const float* __restrict__ b2,
                      float* __restrict__ out) {
    const int tj = threadIdx.x & 15;       // 0..15
    const int ti = threadIdx.x >> 4;       // 0..7
    const int i0 = blockIdx.y * 16 + ti * 2;
    const int j0 = blockIdx.x * 64 + tj * 4;

    // Loop-invariant packed constants over k pairs (kp = k/2).
    u64 u2[8], v2[8], b12[8], t2[8], w2p[8];
#pragma unroll
    for (int kp = 0; kp < 8; ++kp) {
        int ka = 2 * kp, kb = 2 * kp + 1;
        u2[kp]  = f2_pack(W1[ka * 3 + 0], W1[kb * 3 + 0]);
        v2[kp]  = f2_pack(W1[ka * 3 + 1], W1[kb * 3 + 1]);
        t2[kp]  = f2_pack(W1[ka * 3 + 2], W1[kb * 3 + 2]);
        b12[kp] = f2_pack(b1[ka], b1[kb]);
        w2p[kp] = f2_pack(W2[ka], W2[kb]);
    }

    // w_ij for this thread's 2 i x 4 j, broadcast into both f32x2 lanes.
    u64 wij[2][4];
#pragma unroll
    for (int ii = 0; ii < 2; ++ii) {
        float4 wv = *reinterpret_cast<const float4*>(&weight[(size_t)(i0 + ii) * HH + j0]);
        wij[ii][0] = f2_pack(wv.x, wv.x);
        wij[ii][1] = f2_pack(wv.y, wv.y);
        wij[ii][2] = f2_pack(wv.z, wv.z);
        wij[ii][3] = f2_pack(wv.w, wv.w);
    }

    // 8 independent packed accumulator chains (one per (ii,jj)).
    u64 acc[2][4];
#pragma unroll
    for (int ii = 0; ii < 2; ++ii)
#pragma unroll
        for (int jj = 0; jj < 4; ++jj) acc[ii][jj] = 0ull;

#pragma unroll 1
    for (int b = 0; b < BB; ++b) {
        // pre: 2 scalars, identical across all tj in the warp -> broadcast.
        float p0 = pre[(size_t)b * INN + i0];
        float p1 = pre[(size_t)b * INN + i0 + 1];
        u64 pre2[2] = { f2_pack(p0, p0), f2_pack(p1, p1) };
        // post: one float4 per thread, contiguous across tj -> coalesced.
        float4 po = *reinterpret_cast<const float4*>(&post[(size_t)b * HH + j0]);
        u64 post2[4] = { f2_pack(po.x, po.x), f2_pack(po.y, po.y),
                         f2_pack(po.z, po.z), f2_pack(po.w, po.w) };

        // a[ii][kp] = pre_i * u_k + b1_k  (16 packed fma, amortized over 4 j)
        u64 a[2][8];
#pragma unroll
        for (int ii = 0; ii < 2; ++ii)
#pragma unroll
            for (int kp = 0; kp < 8; ++kp)
                a[ii][kp] = f2_fma(pre2[ii], u2[kp], b12[kp]);

#pragma unroll
        for (int ii = 0; ii < 2; ++ii) {
#pragma unroll
            for (int jj = 0; jj < 4; ++jj) {
#pragma unroll
                for (int kp = 0; kp < 8; ++kp) {
                    u64 x = f2_fma(post2[jj], v2[kp], a[ii][kp]);   // + post*v
                    x = f2_fma(wij[ii][jj], t2[kp], x);             // + w*t
                    u64 r = f2_relu(x);                             // relu
                    acc[ii][jj] = f2_fma(r, w2p[kp], acc[ii][jj]);  // += relu*W2
                }
            }
        }
    }

    const float inv_b = 1.0f / (float)BB;
    const float bias2 = b2[0];
#pragma unroll
    for (int ii = 0; ii < 2; ++ii) {
        float4 res;
#pragma unroll
        for (int jj = 0; jj < 4; ++jj) {
            float2 s = f2_unpack(acc[ii][jj]);
            (&res.x)[jj] = fmaf(s.x + s.y, inv_b, bias2);
        }
        *reinterpret_cast<float4*>(&out[(size_t)(i0 + ii) * HH + j0]) = res;
    }
}

// ---------------- launch ----------------
extern "C" void kernel_launch(void* const* d_in, const int* in_sizes, int n_in,
                              void* d_out, int out_size) {
    const float* pre    = (const float*)d_in[0];
    const float* post   = (const float*)d_in[1];
    const float* weight = (const float*)d_in[2];
    const float* W1     = (const float*)d_in[3];
    const float* b1     = (const float*)d_in[4];
    const float* W2     = (const float*)d_in[5];
    const float* b2     = (const float*)d_in[6];
    float* out = (float*)d_out;

    plasticity_fused<<<dim3(HH / 64, INN / 16), 128>>>(
        pre, post, weight, W1, b1, W2, b2, out);
}

// round 4
// speedup vs baseline: 5.5641x; 1.0746x over previous
#include <cuda_runtime.h>

#define BB  64
#define INN 512
#define HH  512
#define HID 16

// ---------------- packed f32x2 helpers (Blackwell sm_100+) ----------------
typedef unsigned long long u64;

static __device__ __forceinline__ u64 f2_fma(u64 a, u64 b, u64 c) {
    u64 r;
    asm("fma.rn.f32x2 %0, %1, %2, %3;" : "=l"(r) : "l"(a), "l"(b), "l"(c));
    return r;
}
static __device__ __forceinline__ u64 f2_pack(float x, float y) {
    u64 r;
    asm("mov.b64 %0, {%1, %2};" : "=l"(r) : "f"(x), "f"(y));
    return r;
}
static __device__ __forceinline__ float2 f2_unpack(u64 v) {
    float2 r;
    asm("mov.b64 {%0, %1}, %2;" : "=f"(r.x), "=f"(r.y) : "l"(v));
    return r;
}
// relu: pack/unpack are register aliasing (free); 2x FMNMX on the alu pipe.
static __device__ __forceinline__ u64 f2_relu(u64 v) {
    float2 t = f2_unpack(v);
    return f2_pack(fmaxf(t.x, 0.0f), fmaxf(t.y, 0.0f));
}

// ---------------- fused kernel ----------------
// out[i,j] = (1/B) * sum_b sum_k relu(pre[b,i]*u_k + post[b,j]*v_k + w_ij*t_k + b1_k) * W2_k + b2
//
// Block: 128 threads = 32 (tj) x 4 (ti). Thread tile: 1 i x 4 j.
// Block tile: 4 i x 128 j. Grid: (512/128, 512/4) = (4, 128) = 512 blocks.
// 2048 warps total -> 13.8 warps/SM; <=128 regs so 4 blocks/SM => ONE wave.
//
// k is processed in two halves (k 0..7, 8..15) so only half the packed
// constants (5 arrays x 4 pairs = 40 regs) are live at a time.
// The b-loop is software-pipelined: next b's pre/post load issues before
// the current b's math, hiding L1/L2 latency.
__global__ __launch_bounds__(128, 4)
void plasticity_fused(const float* __restrict__ pre,
                      const float* __restrict__ post,
                      const float* __restrict__ weight,
                      const float* __restrict__ W1,
                      const float* __restrict__ b1,
                      const float* __restrict__ W2,
                      const float* __restrict__ b2,
                      float* __restrict__ out) {
    const int tj = threadIdx.x & 31;       // 0..31 (lane)
    const int ti = threadIdx.x >> 5;       // 0..3  (warp)
    const int i  = blockIdx.y * 4 + ti;    // one i per thread (warp-uniform)
    const int j0 = blockIdx.x * 128 + tj * 4;

    // w_ij for this thread's 4 j, broadcast into both f32x2 lanes.
    float4 wv = *reinterpret_cast<const float4*>(&weight[(size_t)i * HH + j0]);
    u64 wij[4] = { f2_pack(wv.x, wv.x), f2_pack(wv.y, wv.y),
                   f2_pack(wv.z, wv.z), f2_pack(wv.w, wv.w) };

    // 4 independent packed accumulator chains (one per jj), persist across halves.
    u64 acc[4] = { 0ull, 0ull, 0ull, 0ull };

#pragma unroll 1
    for (int half = 0; half < 2; ++half) {
        const int k0 = half * 8;                 // first k of this half
        // Packed constants for this half: kp = pair index, k = k0 + 2*kp{,+1}.
        u64 u2[4], v2[4], b12[4], t2[4], w2p[4];
#pragma unroll
        for (int kp = 0; kp < 4; ++kp) {
            int ka = k0 + 2 * kp, kb = ka + 1;
            u2[kp]  = f2_pack(W1[ka * 3 + 0], W1[kb * 3 + 0]);
            v2[kp]  = f2_pack(W1[ka * 3 + 1], W1[kb * 3 + 1]);
            t2[kp]  = f2_pack(W1[ka * 3 + 2], W1[kb * 3 + 2]);
            b12[kp] = f2_pack(b1[ka], b1[kb]);
            w2p[kp] = f2_pack(W2[ka], W2[kb]);
        }

        // Software pipeline: prefetch b=0, then in-loop prefetch b+1 (wrapped).
        float  pf_pre  = pre[i];                                   // b = 0
        float4 pf_post = *reinterpret_cast<const float4*>(&post[j0]);

#pragma unroll 1
        for (int b = 0; b < BB; ++b) {
            const float  cp = pf_pre;
            const float4 cq = pf_post;
            const int bn = (b + 1) & (BB - 1);   // wraps to 0 on last iter (harmless reload)
            pf_pre  = pre[(size_t)bn * INN + i];
            pf_post = *reinterpret_cast<const float4*>(&post[(size_t)bn * HH + j0]);

            const u64 pre2 = f2_pack(cp, cp);
            u64 post2[4] = { f2_pack(cq.x, cq.x), f2_pack(cq.y, cq.y),
                             f2_pack(cq.z, cq.z), f2_pack(cq.w, cq.w) };

            // a[kp] = pre_i * u_k + b1_k  (4 packed fma, amortized over 4 j)
            u64 a[4];
#pragma unroll
            for (int kp = 0; kp < 4; ++kp)
                a[kp] = f2_fma(pre2, u2[kp], b12[kp]);

#pragma unroll
            for (int jj = 0; jj < 4; ++jj) {
#pragma unroll
                for (int kp = 0; kp < 4; ++kp) {
                    u64 x = f2_fma(post2[jj], v2[kp], a[kp]);   // + post*v
                    x = f2_fma(wij[jj], t2[kp], x);             // + w*t
                    u64 r = f2_relu(x);                         // relu (2x FMNMX)
                    acc[jj] = f2_fma(r, w2p[kp], acc[jj]);      // += relu*W2
                }
            }
        }
    }

    const float inv_b = 1.0f / (float)BB;
    const float bias2 = b2[0];
    float4 res;
#pragma unroll
    for (int jj = 0; jj < 4; ++jj) {
        float2 s = f2_unpack(acc[jj]);
        (&res.x)[jj] = fmaf(s.x + s.y, inv_b, bias2);
    }
    *reinterpret_cast<float4*>(&out[(size_t)i * HH + j0]) = res;
}

// ---------------- launch ----------------
extern "C" void kernel_launch(void* const* d_in, const int* in_sizes, int n_in,
                              void* d_out, int out_size) {
    const float* pre    = (const float*)d_in[0];
    const float* post   = (const float*)d_in[1];
    const float* weight = (const float*)d_in[2];
    const float* W1     = (const float*)d_in[3];
    const float* b1     = (const float*)d_in[4];
    const float* W2     = (const float*)d_in[5];
    const float* b2     = (const float*)d_in[6];
    float* out = (float*)d_out;

    plasticity_fused<<<dim3(HH / 128, INN / 4), 128>>>(
        pre, post, weight, W1, b1, W2, b2, out);
}

// round 5
// speedup vs baseline: 5.6336x; 1.0125x over previous
#include <cuda_runtime.h>

#define BB  64
#define INN 512
#define HH  512
#define HID 16

// ---------------- packed f32x2 helpers (Blackwell sm_100+) ----------------
typedef unsigned long long u64;

static __device__ __forceinline__ u64 f2_fma(u64 a, u64 b, u64 c) {
    u64 r;
    asm("fma.rn.f32x2 %0, %1, %2, %3;" : "=l"(r) : "l"(a), "l"(b), "l"(c));
    return r;
}
static __device__ __forceinline__ u64 f2_add(u64 a, u64 b) {
    u64 r;
    asm("add.rn.f32x2 %0, %1, %2;" : "=l"(r) : "l"(a), "l"(b));
    return r;
}
static __device__ __forceinline__ u64 f2_pack(float x, float y) {
    u64 r;
    asm("mov.b64 %0, {%1, %2};" : "=l"(r) : "f"(x), "f"(y));
    return r;
}
static __device__ __forceinline__ float2 f2_unpack(u64 v) {
    float2 r;
    asm("mov.b64 {%0, %1}, %2;" : "=f"(r.x), "=f"(r.y) : "l"(v));
    return r;
}
// relu: pack/unpack are register aliasing (free); 2x FMNMX on the alu pipe.
static __device__ __forceinline__ u64 f2_relu(u64 v) {
    float2 t = f2_unpack(v);
    return f2_pack(fmaxf(t.x, 0.0f), fmaxf(t.y, 0.0f));
}

// ---------------- fused kernel ----------------
// out[i,j] = (1/B) * sum_b sum_k relu(pre[b,i]*u_k + post[b,j]*v_k + w_ij*t_k + b1_k) * W2_k + b2
//
// Thread tile: 1 i x 2 j  ->  131072 threads = 4096 warps = 27.7 warps/SM.
// Block: 128 threads = 64 (tj) x 2 (ti). Block tile: 2 i x 128 j.
// Grid: (512/128, 512/2) = (4, 256) = 1024 blocks (~7/SM, single wave).
//
// k processed in two halves (k 0..7, 8..15): only half the packed constants
// (5 arrays x 4 pairs = 40 regs) live at a time. Per-jj accumulator is split
// into even/odd-kp chains (4 chains total) to break acc serialization.
// b-loop software-pipelined via wrap-around prefetch of pre/post.
__global__ __launch_bounds__(128, 6)
void plasticity_fused(const float* __restrict__ pre,
                      const float* __restrict__ post,
                      const float* __restrict__ weight,
                      const float* __restrict__ W1,
                      const float* __restrict__ b1,
                      const float* __restrict__ W2,
                      const float* __restrict__ b2,
                      float* __restrict__ out) {
    const int tj = threadIdx.x & 63;       // 0..63
    const int ti = threadIdx.x >> 6;       // 0..1 (warp-uniform)
    const int i  = blockIdx.y * 2 + ti;
    const int j0 = blockIdx.x * 128 + tj * 2;

    // w_ij for this thread's 2 j, broadcast into both f32x2 lanes.
    float2 wv = *reinterpret_cast<const float2*>(&weight[(size_t)i * HH + j0]);
    u64 wij[2] = { f2_pack(wv.x, wv.x), f2_pack(wv.y, wv.y) };

    // 2 jj x 2 parity accumulator chains, persist across halves.
    u64 acc[2][2] = { {0ull, 0ull}, {0ull, 0ull} };

#pragma unroll 1
    for (int half = 0; half < 2; ++half) {
        const int k0 = half * 8;
        // Packed constants for this half (kp pair index, k = k0 + 2*kp{,+1}).
        u64 u2[4], v2[4], b12[4], t2[4], w2p[4];
#pragma unroll
        for (int kp = 0; kp < 4; ++kp) {
            int ka = k0 + 2 * kp, kb = ka + 1;
            u2[kp]  = f2_pack(W1[ka * 3 + 0], W1[kb * 3 + 0]);
            v2[kp]  = f2_pack(W1[ka * 3 + 1], W1[kb * 3 + 1]);
            t2[kp]  = f2_pack(W1[ka * 3 + 2], W1[kb * 3 + 2]);
            b12[kp] = f2_pack(b1[ka], b1[kb]);
            w2p[kp] = f2_pack(W2[ka], W2[kb]);
        }

        // Software pipeline: prefetch b=0, then in-loop prefetch b+1 (wrapped).
        float  pf_pre  = pre[i];
        float2 pf_post = *reinterpret_cast<const float2*>(&post[j0]);

#pragma unroll 1
        for (int b = 0; b < BB; ++b) {
            const float  cp = pf_pre;
            const float2 cq = pf_post;
            const int bn = (b + 1) & (BB - 1);   // wraps to 0 (harmless reload)
            pf_pre  = pre[(size_t)bn * INN + i];
            pf_post = *reinterpret_cast<const float2*>(&post[(size_t)bn * HH + j0]);

            const u64 pre2 = f2_pack(cp, cp);
            const u64 post2[2] = { f2_pack(cq.x, cq.x), f2_pack(cq.y, cq.y) };

            // a[kp] = pre_i * u_k + b1_k  (4 packed fma, shared by both jj)
            u64 a[4];
#pragma unroll
            for (int kp = 0; kp < 4; ++kp)
                a[kp] = f2_fma(pre2, u2[kp], b12[kp]);

#pragma unroll
            for (int jj = 0; jj < 2; ++jj) {
#pragma unroll
                for (int kp = 0; kp < 4; ++kp) {
                    u64 x = f2_fma(post2[jj], v2[kp], a[kp]);      // + post*v
                    x = f2_fma(wij[jj], t2[kp], x);                // + w*t
                    u64 r = f2_relu(x);                            // relu (2x FMNMX)
                    acc[jj][kp & 1] = f2_fma(r, w2p[kp], acc[jj][kp & 1]);
                }
            }
        }
    }

    const float inv_b = 1.0f / (float)BB;
    const float bias2 = b2[0];
    float2 res;
#pragma unroll
    for (int jj = 0; jj < 2; ++jj) {
        float2 s = f2_unpack(f2_add(acc[jj][0], acc[jj][1]));
        (&res.x)[jj] = fmaf(s.x + s.y, inv_b, bias2);
    }
    *reinterpret_cast<float2*>(&out[(size_t)i * HH + j0]) = res;
}

// ---------------- launch ----------------
extern "C" void kernel_launch(void* const* d_in, const int* in_sizes, int n_in,
                              void* d_out, int out_size) {
    const float* pre    = (const float*)d_in[0];
    const float* post   = (const float*)d_in[1];
    const float* weight = (const float*)d_in[2];
    const float* W1     = (const float*)d_in[3];
    const float* b1     = (const float*)d_in[4];
    const float* W2     = (const float*)d_in[5];
    const float* b2     = (const float*)d_in[6];
    float* out = (float*)d_out;

    plasticity_fused<<<dim3(HH / 128, INN / 2), 128>>>(
        pre, post, weight, W1, b1, W2, b2, out);
}